// round 1
// baseline (speedup 1.0000x reference)
#include <cuda_runtime.h>
#include <cuda_bf16.h>

// Problem constants (EdgeNetwork, fixed shapes)
#define BB 2
#define NN 1024
#define DD 16
#define HH 8

// Scratch for precomputed per-row projections (device globals: allocation-free)
__device__ float g_tj [BB * NN * HH];   // t_j[b,n,h]
__device__ float g_tiv[BB * NN * HH];   // t_i[b,n,h] + t_v[b,h] + b1[h]

__device__ __forceinline__ float fast_tanh(float x) {
    // tanh(x) = 1 - 2/(exp(2x)+1). MUFU.EX2 + MUFU.RCP; abs err ~1e-7.
    float u = __expf(2.0f * x);
    return 1.0f - __fdividef(2.0f, u + 1.0f);
}

// ---------------------------------------------------------------------------
// Kernel 1: precompute t_j and (t_i + t_v + b1) for every (b, n).
// 2048 threads total; trivial cost.
// ---------------------------------------------------------------------------
__global__ void precompute_kernel(const float* __restrict__ x,
                                  const float* __restrict__ vp,
                                  const float* __restrict__ W1,
                                  const float* __restrict__ b1) {
    int idx = blockIdx.x * blockDim.x + threadIdx.x;   // b*NN + n
    if (idx >= BB * NN) return;
    int b = idx >> 10;

    float xv[DD];
#pragma unroll
    for (int c = 0; c < DD; c++) xv[c] = x[idx * DD + c];
    float vv[DD];
#pragma unroll
    for (int c = 0; c < DD; c++) vv[c] = vp[b * DD + c];

#pragma unroll
    for (int h = 0; h < HH; h++) {
        const float* wr = W1 + h * (3 * DD + 1);
        float tj = 0.0f, ti = 0.0f, tv = 0.0f;
#pragma unroll
        for (int c = 0; c < DD; c++) {
            tj += xv[c] * wr[c];
            ti += xv[c] * wr[DD + c];
            tv += vv[c] * wr[2 * DD + c];
        }
        g_tj [idx * HH + h] = tj;
        g_tiv[idx * HH + h] = ti + tv + b1[h];
    }
}

// ---------------------------------------------------------------------------
// Kernel 2: main edge MLP. Block = 256 threads = 32 i x 8 "j-quads";
// each thread computes 4 edges (1 i, 4 consecutive j).
// ---------------------------------------------------------------------------
__global__ __launch_bounds__(256, 2)
void edge_mlp_kernel(const float* __restrict__ A,
                     const float* __restrict__ W1,
                     const float* __restrict__ W2, const float* __restrict__ b2,
                     const float* __restrict__ W3, const float* __restrict__ b3,
                     const float* __restrict__ W4, const float* __restrict__ b4,
                     const float* __restrict__ W5, const float* __restrict__ b5,
                     float* __restrict__ out) {
    __shared__ float s_tj[32 * HH];     // j tile
    __shared__ float s_ti[32 * HH];     // i tile (already + t_v + b1)
    __shared__ float s_w [3][HH * HH];  // W2, W3, W4 as [k*8+h]
    __shared__ float s_b [3][HH];
    __shared__ float s_w5[HH];
    __shared__ float s_w1a[HH];
    __shared__ float s_b5;

    const int tid = threadIdx.x;
    const int b  = blockIdx.z;
    const int i0 = blockIdx.y * 32;
    const int j0 = blockIdx.x * 32;

    // --- cooperative loads ---
    {
        // 32*8 = 256 elements each; one per thread
        int n  = tid >> 3;
        int h  = tid & 7;
        s_tj[tid] = g_tj [(b * NN + j0 + n) * HH + h];
        s_ti[tid] = g_tiv[(b * NN + i0 + n) * HH + h];
        if (tid < 64) {
            s_w[0][tid] = W2[tid];
            s_w[1][tid] = W3[tid];
            s_w[2][tid] = W4[tid];
        }
        if (tid < 8) {
            s_b[0][tid] = b2[tid];
            s_b[1][tid] = b3[tid];
            s_b[2][tid] = b4[tid];
            s_w5[tid]  = W5[tid];
            s_w1a[tid] = W1[tid * (3 * DD + 1) + 3 * DD];   // W1[:,48]
        }
        if (tid == 0) s_b5 = b5[0];
    }
    __syncthreads();

    const int ii = tid >> 3;         // 0..31
    const int jq = tid & 7;          // 0..7  -> 4 j's each
    const int jl = jq * 4;

    // Per-thread register copies of small vectors
    float tiv[HH], w1a[HH], w5r[HH];
#pragma unroll
    for (int h = 0; h < HH; h++) {
        tiv[h] = s_ti[ii * HH + h];
        w1a[h] = s_w1a[h];
        w5r[h] = s_w5[h];
    }

    // Coalesced A load: 4 consecutive j per thread
    const long row = (long)(b * NN + i0 + ii) * NN + j0 + jl;
    float4 a4 = *reinterpret_cast<const float4*>(A + row);
    float a[4] = {a4.x, a4.y, a4.z, a4.w};

    // --- layer 1 ---
    float hcur[4][HH];
#pragma unroll
    for (int e = 0; e < 4; e++) {
#pragma unroll
        for (int h = 0; h < HH; h++) {
            float pre = s_tj[(jl + e) * HH + h] + tiv[h] + a[e] * w1a[h];
            hcur[e][h] = fast_tanh(pre);
        }
    }

    // --- layers 2..4 ---
#pragma unroll
    for (int l = 0; l < 3; l++) {
        float acc[4][HH];
#pragma unroll
        for (int k = 0; k < HH; k++) {
            float bk = s_b[l][k];
            acc[0][k] = bk; acc[1][k] = bk; acc[2][k] = bk; acc[3][k] = bk;
        }
#pragma unroll
        for (int k = 0; k < HH; k++) {
#pragma unroll
            for (int h = 0; h < HH; h++) {
                float w = s_w[l][k * HH + h];
#pragma unroll
                for (int e = 0; e < 4; e++)
                    acc[e][k] += hcur[e][h] * w;
            }
        }
#pragma unroll
        for (int e = 0; e < 4; e++)
#pragma unroll
            for (int k = 0; k < HH; k++)
                hcur[e][k] = fast_tanh(acc[e][k]);
    }

    // --- output layer ---
    float o[4];
#pragma unroll
    for (int e = 0; e < 4; e++) {
        float v = s_b5;
#pragma unroll
        for (int h = 0; h < HH; h++)
            v += hcur[e][h] * w5r[h];
        o[e] = v;
    }
    float4 o4 = make_float4(o[0], o[1], o[2], o[3]);
    *reinterpret_cast<float4*>(out + row) = o4;
}

// ---------------------------------------------------------------------------
extern "C" void kernel_launch(void* const* d_in, const int* in_sizes, int n_in,
                              void* d_out, int out_size) {
    const float* x  = (const float*)d_in[0];
    const float* A  = (const float*)d_in[1];
    const float* vp = (const float*)d_in[2];
    const float* W1 = (const float*)d_in[3];
    const float* b1 = (const float*)d_in[4];
    const float* W2 = (const float*)d_in[5];
    const float* b2 = (const float*)d_in[6];
    const float* W3 = (const float*)d_in[7];
    const float* b3 = (const float*)d_in[8];
    const float* W4 = (const float*)d_in[9];
    const float* b4 = (const float*)d_in[10];
    const float* W5 = (const float*)d_in[11];
    const float* b5 = (const float*)d_in[12];
    float* out = (float*)d_out;

    precompute_kernel<<<(BB * NN + 255) / 256, 256>>>(x, vp, W1, b1);

    dim3 grid(NN / 32, NN / 32, BB);   // 32 x 32 x 2 = 2048 blocks
    edge_mlp_kernel<<<grid, 256>>>(A, W1, W2, b2, W3, b3, W4, b4, W5, b5, out);
}

// round 2
// speedup vs baseline: 1.4105x; 1.4105x over previous
#include <cuda_runtime.h>
#include <cuda_bf16.h>

// Problem constants (EdgeNetwork, fixed shapes)
#define BB 2
#define NN 1024
#define DD 16
#define HH 8
#define W1STRIDE (3 * DD + 1)   // 49

__device__ __forceinline__ float tanh_approx(float x) {
    float y;
    asm("tanh.approx.f32 %0, %1;" : "=f"(y) : "f"(x));
    return y;
}

// ---------------------------------------------------------------------------
// Single fused kernel. Block = 256 threads = 32 i x 8 "j-quads";
// each thread computes 4 edges (1 i, 4 consecutive j).
// Layer-1 row projections (t_j, t_i + t_v + b1) are recomputed per block
// from x (cost ~2.7% of block work; saves a kernel launch + global roundtrip).
// ---------------------------------------------------------------------------
__global__ __launch_bounds__(256, 2)
void edge_mlp_kernel(const float* __restrict__ x,
                     const float* __restrict__ A,
                     const float* __restrict__ vp,
                     const float* __restrict__ W1, const float* __restrict__ b1,
                     const float* __restrict__ W2, const float* __restrict__ b2,
                     const float* __restrict__ W3, const float* __restrict__ b3,
                     const float* __restrict__ W4, const float* __restrict__ b4,
                     const float* __restrict__ W5, const float* __restrict__ b5,
                     float* __restrict__ out) {
    __shared__ float s_xj[32][DD];      // x rows for j tile
    __shared__ float s_xi[32][DD];      // x rows for i tile
    __shared__ float s_w1[HH * W1STRIDE];
    __shared__ float s_tj[32 * HH];     // t_j
    __shared__ float s_ti[32 * HH];     // t_i + t_v + b1
    __shared__ float s_w [3][HH * HH];  // W2, W3, W4 as [k*8+h]
    __shared__ float s_b [3][HH];
    __shared__ float s_w5[HH];
    __shared__ float s_w1a[HH];
    __shared__ float s_b5;

    const int tid = threadIdx.x;
    const int b  = blockIdx.z;
    const int i0 = blockIdx.y * 32;
    const int j0 = blockIdx.x * 32;

    // --- phase 1: load x rows + all weights into shared ---
    {
        // 64 rows x 16 floats = 1024 floats = 256 threads x 1 float4
        int row = tid >> 2;            // 0..63
        int c4  = (tid & 3) * 4;
        if (row < 32) {
            float4 v = *reinterpret_cast<const float4*>(x + ((size_t)(b * NN + j0 + row)) * DD + c4);
            s_xj[row][c4] = v.x; s_xj[row][c4 + 1] = v.y;
            s_xj[row][c4 + 2] = v.z; s_xj[row][c4 + 3] = v.w;
        } else {
            int r = row - 32;
            float4 v = *reinterpret_cast<const float4*>(x + ((size_t)(b * NN + i0 + r)) * DD + c4);
            s_xi[r][c4] = v.x; s_xi[r][c4 + 1] = v.y;
            s_xi[r][c4 + 2] = v.z; s_xi[r][c4 + 3] = v.w;
        }
        // W1: 8*49 = 392 floats
        if (tid < HH * W1STRIDE - 256) s_w1[256 + tid] = W1[256 + tid];
        s_w1[tid] = W1[tid];
        if (tid < 64) {
            s_w[0][tid] = W2[tid];
            s_w[1][tid] = W3[tid];
            s_w[2][tid] = W4[tid];
        }
        if (tid < 8) {
            s_b[0][tid] = b2[tid];
            s_b[1][tid] = b3[tid];
            s_b[2][tid] = b4[tid];
            s_w5[tid]  = W5[tid];
            s_w1a[tid] = W1[tid * W1STRIDE + 3 * DD];
        }
        if (tid == 0) s_b5 = b5[0];
    }
    __syncthreads();

    // --- phase 2: per-row projections (256 (n,h) pairs, one per thread) ---
    {
        int n = tid >> 3;      // 0..31
        int h = tid & 7;       // 0..7
        const float* wr = s_w1 + h * W1STRIDE;
        float tj = 0.0f, ti = 0.0f;
#pragma unroll
        for (int c = 0; c < DD; c++) {
            tj += s_xj[n][c] * wr[c];
            ti += s_xi[n][c] * wr[DD + c];
        }
        float tv = b1[h];
#pragma unroll
        for (int c = 0; c < DD; c++)
            tv += vp[b * DD + c] * wr[2 * DD + c];
        s_tj[tid] = tj;
        s_ti[tid] = ti + tv;
    }
    __syncthreads();

    // --- phase 3: main edge MLP ---
    const int ii = tid >> 3;         // 0..31
    const int jl = (tid & 7) * 4;    // 0,4,...,28

    float tiv[HH], w1a[HH], w5r[HH];
#pragma unroll
    for (int h = 0; h < HH; h++) {
        tiv[h] = s_ti[ii * HH + h];
        w1a[h] = s_w1a[h];
        w5r[h] = s_w5[h];
    }

    const size_t row = ((size_t)(b * NN + i0 + ii)) * NN + j0 + jl;
    float4 a4 = *reinterpret_cast<const float4*>(A + row);
    float a[4] = {a4.x, a4.y, a4.z, a4.w};

    // layer 1
    float hcur[4][HH];
#pragma unroll
    for (int e = 0; e < 4; e++) {
#pragma unroll
        for (int h = 0; h < HH; h++) {
            float pre = s_tj[(jl + e) * HH + h] + tiv[h] + a[e] * w1a[h];
            hcur[e][h] = tanh_approx(pre);
        }
    }

    // layers 2..4
#pragma unroll
    for (int l = 0; l < 3; l++) {
        float acc[4][HH];
#pragma unroll
        for (int k = 0; k < HH; k++) {
            float bk = s_b[l][k];
            acc[0][k] = bk; acc[1][k] = bk; acc[2][k] = bk; acc[3][k] = bk;
        }
#pragma unroll
        for (int k = 0; k < HH; k++) {
#pragma unroll
            for (int h = 0; h < HH; h++) {
                float w = s_w[l][k * HH + h];
#pragma unroll
                for (int e = 0; e < 4; e++)
                    acc[e][k] += hcur[e][h] * w;
            }
        }
#pragma unroll
        for (int e = 0; e < 4; e++)
#pragma unroll
            for (int k = 0; k < HH; k++)
                hcur[e][k] = tanh_approx(acc[e][k]);
    }

    // output layer
    float o[4];
#pragma unroll
    for (int e = 0; e < 4; e++) {
        float v = s_b5;
#pragma unroll
        for (int h = 0; h < HH; h++)
            v += hcur[e][h] * w5r[h];
        o[e] = v;
    }
    *reinterpret_cast<float4*>(out + row) = make_float4(o[0], o[1], o[2], o[3]);
}

// ---------------------------------------------------------------------------
extern "C" void kernel_launch(void* const* d_in, const int* in_sizes, int n_in,
                              void* d_out, int out_size) {
    const float* x  = (const float*)d_in[0];
    const float* A  = (const float*)d_in[1];
    const float* vp = (const float*)d_in[2];
    const float* W1 = (const float*)d_in[3];
    const float* b1 = (const float*)d_in[4];
    const float* W2 = (const float*)d_in[5];
    const float* b2 = (const float*)d_in[6];
    const float* W3 = (const float*)d_in[7];
    const float* b3 = (const float*)d_in[8];
    const float* W4 = (const float*)d_in[9];
    const float* b4 = (const float*)d_in[10];
    const float* W5 = (const float*)d_in[11];
    const float* b5 = (const float*)d_in[12];
    float* out = (float*)d_out;

    dim3 grid(NN / 32, NN / 32, BB);   // 32 x 32 x 2 = 2048 blocks
    edge_mlp_kernel<<<grid, 256>>>(x, A, vp, W1, b1, W2, b2, W3, b3,
                                   W4, b4, W5, b5, out);
}

// round 3
// speedup vs baseline: 1.7225x; 1.2212x over previous
#include <cuda_runtime.h>
#include <cuda_bf16.h>

#define BB 2
#define NN 1024
#define DD 16
#define HH 8
#define W1STRIDE (3 * DD + 1)   // 49

typedef unsigned long long ull;

__device__ __forceinline__ float tanh_approx(float x) {
    float y;
    asm("tanh.approx.f32 %0, %1;" : "=f"(y) : "f"(x));
    return y;
}
__device__ __forceinline__ ull pack2(float lo, float hi) {
    ull d;
    asm("mov.b64 %0, {%1, %2};" : "=l"(d) : "f"(lo), "f"(hi));
    return d;
}
__device__ __forceinline__ void unpack2(ull v, float& lo, float& hi) {
    asm("mov.b64 {%0, %1}, %2;" : "=f"(lo), "=f"(hi) : "l"(v));
}
__device__ __forceinline__ ull fma2(ull a, ull b, ull c) {
    ull d;
    asm("fma.rn.f32x2 %0, %1, %2, %3;" : "=l"(d) : "l"(a), "l"(b), "l"(c));
    return d;
}
__device__ __forceinline__ ull add2(ull a, ull b) {
    ull d;
    asm("add.rn.f32x2 %0, %1, %2;" : "=l"(d) : "l"(a), "l"(b));
    return d;
}

// ---------------------------------------------------------------------------
// Fused kernel. Block = 256 threads = 32 i x 8 j-quads; 4 edges/thread,
// processed as 2 packed f32x2 lanes (FFMA2 dual-issue FP32 path).
// ---------------------------------------------------------------------------
__global__ __launch_bounds__(256, 2)
void edge_mlp_kernel(const float* __restrict__ x,
                     const float* __restrict__ A,
                     const float* __restrict__ vp,
                     const float* __restrict__ W1, const float* __restrict__ b1,
                     const float* __restrict__ W2, const float* __restrict__ b2,
                     const float* __restrict__ W3, const float* __restrict__ b3,
                     const float* __restrict__ W4, const float* __restrict__ b4,
                     const float* __restrict__ W5, const float* __restrict__ b5,
                     float* __restrict__ out) {
    __shared__ float s_xj[32][DD];
    __shared__ float s_xi[32][DD];
    __shared__ float s_w1[HH * W1STRIDE];
    __shared__ float s_tjt[HH][32];      // t_j transposed: [h][j]
    __shared__ float s_ti[32 * HH];      // t_i + t_v + b1, [i][h]
    __shared__ ull   s_wd[3][HH * HH];   // W2/3/4 duplicated pairs (w,w)
    __shared__ ull   s_bd[3][HH];        // biases duplicated
    __shared__ ull   s_w5d[HH];
    __shared__ ull   s_w1ad[HH];
    __shared__ ull   s_b5d;

    const int tid = threadIdx.x;
    const int b  = blockIdx.z;
    const int i0 = blockIdx.y * 32;
    const int j0 = blockIdx.x * 32;

    // --- phase 1: load x rows + all weights into shared ---
    {
        int row = tid >> 2;
        int c4  = (tid & 3) * 4;
        if (row < 32) {
            float4 v = *reinterpret_cast<const float4*>(x + ((size_t)(b * NN + j0 + row)) * DD + c4);
            s_xj[row][c4] = v.x; s_xj[row][c4 + 1] = v.y;
            s_xj[row][c4 + 2] = v.z; s_xj[row][c4 + 3] = v.w;
        } else {
            int r = row - 32;
            float4 v = *reinterpret_cast<const float4*>(x + ((size_t)(b * NN + i0 + r)) * DD + c4);
            s_xi[r][c4] = v.x; s_xi[r][c4 + 1] = v.y;
            s_xi[r][c4 + 2] = v.z; s_xi[r][c4 + 3] = v.w;
        }
        if (tid < HH * W1STRIDE - 256) s_w1[256 + tid] = W1[256 + tid];
        s_w1[tid] = W1[tid];
        if (tid < 64) {
            float w2 = W2[tid], w3 = W3[tid], w4 = W4[tid];
            s_wd[0][tid] = pack2(w2, w2);
            s_wd[1][tid] = pack2(w3, w3);
            s_wd[2][tid] = pack2(w4, w4);
        }
        if (tid < 8) {
            float v2 = b2[tid], v3 = b3[tid], v4 = b4[tid];
            s_bd[0][tid] = pack2(v2, v2);
            s_bd[1][tid] = pack2(v3, v3);
            s_bd[2][tid] = pack2(v4, v4);
            float w5 = W5[tid];
            s_w5d[tid] = pack2(w5, w5);
            float wa = W1[tid * W1STRIDE + 3 * DD];
            s_w1ad[tid] = pack2(wa, wa);
        }
        if (tid == 0) { float v = b5[0]; s_b5d = pack2(v, v); }
    }
    __syncthreads();

    const int ii = tid >> 3;         // 0..31
    const int jl = (tid & 7) * 4;    // 0,4,...,28

    // Issue the A load early to overlap with phase 2 compute
    const size_t row = ((size_t)(b * NN + i0 + ii)) * NN + j0 + jl;
    float4 a4 = *reinterpret_cast<const float4*>(A + row);

    // --- phase 2: per-row projections (256 (n,h) pairs, one per thread) ---
    {
        int n = tid >> 3;
        int h = tid & 7;
        const float* wr = s_w1 + h * W1STRIDE;
        float tj = 0.0f, ti = 0.0f;
#pragma unroll
        for (int c = 0; c < DD; c++) {
            tj += s_xj[n][c] * wr[c];
            ti += s_xi[n][c] * wr[DD + c];
        }
        float tv = b1[h];
#pragma unroll
        for (int c = 0; c < DD; c++)
            tv += vp[b * DD + c] * wr[2 * DD + c];
        s_tjt[h][n] = tj;
        s_ti[n * HH + h] = ti + tv;
    }
    __syncthreads();

    // --- phase 3: packed edge MLP (2 f32x2 lanes = 4 edges) ---
    ull tiv2[HH];
#pragma unroll
    for (int h = 0; h < HH; h++) {
        float t = s_ti[ii * HH + h];
        tiv2[h] = pack2(t, t);
    }
    ull a2[2] = { pack2(a4.x, a4.y), pack2(a4.z, a4.w) };

    // layer 1
    ull h2[2][HH];
#pragma unroll
    for (int p = 0; p < 2; p++) {
#pragma unroll
        for (int h = 0; h < HH; h++) {
            ull tj2 = *reinterpret_cast<const ull*>(&s_tjt[h][jl + 2 * p]);
            ull pre = fma2(a2[p], s_w1ad[h], add2(tj2, tiv2[h]));
            float lo, hi;
            unpack2(pre, lo, hi);
            h2[p][h] = pack2(tanh_approx(lo), tanh_approx(hi));
        }
    }

    // layers 2..4
#pragma unroll
    for (int l = 0; l < 3; l++) {
        ull acc[2][HH];
#pragma unroll
        for (int k = 0; k < HH; k++) {
            ull bk = s_bd[l][k];
            acc[0][k] = bk;
            acc[1][k] = bk;
        }
#pragma unroll
        for (int k = 0; k < HH; k++) {
#pragma unroll
            for (int h = 0; h < HH; h++) {
                ull w = s_wd[l][k * HH + h];
                acc[0][k] = fma2(h2[0][h], w, acc[0][k]);
                acc[1][k] = fma2(h2[1][h], w, acc[1][k]);
            }
        }
#pragma unroll
        for (int p = 0; p < 2; p++)
#pragma unroll
            for (int k = 0; k < HH; k++) {
                float lo, hi;
                unpack2(acc[p][k], lo, hi);
                h2[p][k] = pack2(tanh_approx(lo), tanh_approx(hi));
            }
    }

    // output layer
    ull o2[2] = { s_b5d, s_b5d };
#pragma unroll
    for (int h = 0; h < HH; h++) {
        ull w = s_w5d[h];
        o2[0] = fma2(h2[0][h], w, o2[0]);
        o2[1] = fma2(h2[1][h], w, o2[1]);
    }
    float4 o4;
    unpack2(o2[0], o4.x, o4.y);
    unpack2(o2[1], o4.z, o4.w);
    *reinterpret_cast<float4*>(out + row) = o4;
}

// ---------------------------------------------------------------------------
extern "C" void kernel_launch(void* const* d_in, const int* in_sizes, int n_in,
                              void* d_out, int out_size) {
    const float* x  = (const float*)d_in[0];
    const float* A  = (const float*)d_in[1];
    const float* vp = (const float*)d_in[2];
    const float* W1 = (const float*)d_in[3];
    const float* b1 = (const float*)d_in[4];
    const float* W2 = (const float*)d_in[5];
    const float* b2 = (const float*)d_in[6];
    const float* W3 = (const float*)d_in[7];
    const float* b3 = (const float*)d_in[8];
    const float* W4 = (const float*)d_in[9];
    const float* b4 = (const float*)d_in[10];
    const float* W5 = (const float*)d_in[11];
    const float* b5 = (const float*)d_in[12];
    float* out = (float*)d_out;

    dim3 grid(NN / 32, NN / 32, BB);
    edge_mlp_kernel<<<grid, 256>>>(x, A, vp, W1, b1, W2, b2, W3, b3,
                                   W4, b4, W5, b5, out);
}

// round 4
// speedup vs baseline: 1.8220x; 1.0578x over previous
#include <cuda_runtime.h>
#include <cuda_bf16.h>

#define BB 2
#define NN 1024
#define DD 16
#define HH 8
#define W1STRIDE (3 * DD + 1)   // 49

typedef unsigned long long ull;

__device__ __forceinline__ float tanh_approx(float x) {
    float y;
    asm("tanh.approx.f32 %0, %1;" : "=f"(y) : "f"(x));
    return y;
}
__device__ __forceinline__ ull pack2(float lo, float hi) {
    ull d;
    asm("mov.b64 %0, {%1, %2};" : "=l"(d) : "f"(lo), "f"(hi));
    return d;
}
__device__ __forceinline__ void unpack2(ull v, float& lo, float& hi) {
    asm("mov.b64 {%0, %1}, %2;" : "=f"(lo), "=f"(hi) : "l"(v));
}
__device__ __forceinline__ ull fma2(ull a, ull b, ull c) {
    ull d;
    asm("fma.rn.f32x2 %0, %1, %2, %3;" : "=l"(d) : "l"(a), "l"(b), "l"(c));
    return d;
}
__device__ __forceinline__ ull add2(ull a, ull b) {
    ull d;
    asm("add.rn.f32x2 %0, %1, %2;" : "=l"(d) : "l"(a), "l"(b));
    return d;
}

// ---------------------------------------------------------------------------
// Fused kernel. Block = 256 threads = 32 i x 8 j-quads; 4 edges/thread as
// 2 packed f32x2 lanes. Weights duplicated (w,w) and TRANSPOSED to [h][k]
// so LDS.128 loads 2 pairs and all 16 acc chains stay independent.
// ---------------------------------------------------------------------------
__global__ __launch_bounds__(256, 2)
void edge_mlp_kernel(const float* __restrict__ x,
                     const float* __restrict__ A,
                     const float* __restrict__ vp,
                     const float* __restrict__ W1, const float* __restrict__ b1,
                     const float* __restrict__ W2, const float* __restrict__ b2,
                     const float* __restrict__ W3, const float* __restrict__ b3,
                     const float* __restrict__ W4, const float* __restrict__ b4,
                     const float* __restrict__ W5, const float* __restrict__ b5,
                     float* __restrict__ out) {
    __shared__ __align__(16) float s_xj[32][DD];
    __shared__ __align__(16) float s_xi[32][DD];
    __shared__ __align__(16) float s_w1[HH * W1STRIDE];
    __shared__ __align__(16) float s_tjt[HH][32];     // t_j transposed [h][j]
    __shared__ __align__(16) float s_ti[32 * HH];     // t_i + t_v + b1, [i][h]
    __shared__ __align__(16) ull   s_wd[3][HH * HH];  // W-l transposed: [h][k], dup pairs
    __shared__ __align__(16) ull   s_bd[3][HH];       // biases dup pairs
    __shared__ __align__(16) ull   s_w5d[HH];
    __shared__ __align__(16) ull   s_w1ad[HH];
    __shared__ ull   s_b5d;

    const int tid = threadIdx.x;
    const int b  = blockIdx.z;
    const int i0 = blockIdx.y * 32;
    const int j0 = blockIdx.x * 32;

    // --- phase 1: load x rows + all weights into shared ---
    {
        int row = tid >> 2;
        int c4  = (tid & 3) * 4;
        if (row < 32) {
            float4 v = *reinterpret_cast<const float4*>(x + ((size_t)(b * NN + j0 + row)) * DD + c4);
            s_xj[row][c4] = v.x; s_xj[row][c4 + 1] = v.y;
            s_xj[row][c4 + 2] = v.z; s_xj[row][c4 + 3] = v.w;
        } else {
            int r = row - 32;
            float4 v = *reinterpret_cast<const float4*>(x + ((size_t)(b * NN + i0 + r)) * DD + c4);
            s_xi[r][c4] = v.x; s_xi[r][c4 + 1] = v.y;
            s_xi[r][c4 + 2] = v.z; s_xi[r][c4 + 3] = v.w;
        }
        if (tid < HH * W1STRIDE - 256) s_w1[256 + tid] = W1[256 + tid];
        s_w1[tid] = W1[tid];
        if (tid < 64) {
            // source index: k = tid>>3, h = tid&7 ; dest transposed: [h][k]
            int dstT = (tid & 7) * HH + (tid >> 3);
            float w2 = W2[tid], w3 = W3[tid], w4 = W4[tid];
            s_wd[0][dstT] = pack2(w2, w2);
            s_wd[1][dstT] = pack2(w3, w3);
            s_wd[2][dstT] = pack2(w4, w4);
        }
        if (tid < 8) {
            float v2 = b2[tid], v3 = b3[tid], v4 = b4[tid];
            s_bd[0][tid] = pack2(v2, v2);
            s_bd[1][tid] = pack2(v3, v3);
            s_bd[2][tid] = pack2(v4, v4);
            float w5 = W5[tid];
            s_w5d[tid] = pack2(w5, w5);
            float wa = W1[tid * W1STRIDE + 3 * DD];
            s_w1ad[tid] = pack2(wa, wa);
        }
        if (tid == 0) { float v = b5[0]; s_b5d = pack2(v, v); }
    }
    __syncthreads();

    const int ii = tid >> 3;         // 0..31
    const int jl = (tid & 7) * 4;    // 0,4,...,28

    // Early global A load to overlap with phase 2
    const size_t row = ((size_t)(b * NN + i0 + ii)) * NN + j0 + jl;
    float4 a4 = *reinterpret_cast<const float4*>(A + row);

    // --- phase 2: per-row projections ---
    {
        int n = tid >> 3;
        int h = tid & 7;
        const float* wr = s_w1 + h * W1STRIDE;
        float tj = 0.0f, ti = 0.0f;
#pragma unroll
        for (int c = 0; c < DD; c++) {
            tj += s_xj[n][c] * wr[c];
            ti += s_xi[n][c] * wr[DD + c];
        }
        float tv = b1[h];
#pragma unroll
        for (int c = 0; c < DD; c++)
            tv += vp[b * DD + c] * wr[2 * DD + c];
        s_tjt[h][n] = tj;
        s_ti[n * HH + h] = ti + tv;
    }
    __syncthreads();

    // --- phase 3: packed edge MLP ---
    // Per-thread register copies (LDS.128 loads)
    ull w1ad[HH], w5d[HH];
#pragma unroll
    for (int h = 0; h < HH; h += 2) {
        ulonglong2 wa = *reinterpret_cast<const ulonglong2*>(&s_w1ad[h]);
        w1ad[h] = wa.x; w1ad[h + 1] = wa.y;
        ulonglong2 w5 = *reinterpret_cast<const ulonglong2*>(&s_w5d[h]);
        w5d[h] = w5.x; w5d[h + 1] = w5.y;
    }
    ull tiv2[HH];
#pragma unroll
    for (int h = 0; h < HH; h += 4) {
        float4 t = *reinterpret_cast<const float4*>(&s_ti[ii * HH + h]);
        tiv2[h]     = pack2(t.x, t.x);
        tiv2[h + 1] = pack2(t.y, t.y);
        tiv2[h + 2] = pack2(t.z, t.z);
        tiv2[h + 3] = pack2(t.w, t.w);
    }
    ull a2[2] = { pack2(a4.x, a4.y), pack2(a4.z, a4.w) };

    // layer 1: one float4 per h covers both lanes' t_j
    ull h2[2][HH];
#pragma unroll
    for (int h = 0; h < HH; h++) {
        float4 tj4 = *reinterpret_cast<const float4*>(&s_tjt[h][jl]);
        ull pre0 = fma2(a2[0], w1ad[h], add2(pack2(tj4.x, tj4.y), tiv2[h]));
        ull pre1 = fma2(a2[1], w1ad[h], add2(pack2(tj4.z, tj4.w), tiv2[h]));
        float l0, l1, l2, l3;
        unpack2(pre0, l0, l1);
        unpack2(pre1, l2, l3);
        h2[0][h] = pack2(tanh_approx(l0), tanh_approx(l1));
        h2[1][h] = pack2(tanh_approx(l2), tanh_approx(l3));
    }

    // layers 2..4: h outer, k inner (16 independent acc chains)
#pragma unroll
    for (int l = 0; l < 3; l++) {
        ull acc[2][HH];
#pragma unroll
        for (int k = 0; k < HH; k += 2) {
            ulonglong2 bk = *reinterpret_cast<const ulonglong2*>(&s_bd[l][k]);
            acc[0][k] = bk.x; acc[1][k] = bk.x;
            acc[0][k + 1] = bk.y; acc[1][k + 1] = bk.y;
        }
#pragma unroll
        for (int h = 0; h < HH; h++) {
            ull hv0 = h2[0][h];
            ull hv1 = h2[1][h];
#pragma unroll
            for (int kp = 0; kp < HH / 2; kp++) {
                ulonglong2 w = *reinterpret_cast<const ulonglong2*>(&s_wd[l][h * HH + kp * 2]);
                acc[0][kp * 2]     = fma2(hv0, w.x, acc[0][kp * 2]);
                acc[1][kp * 2]     = fma2(hv1, w.x, acc[1][kp * 2]);
                acc[0][kp * 2 + 1] = fma2(hv0, w.y, acc[0][kp * 2 + 1]);
                acc[1][kp * 2 + 1] = fma2(hv1, w.y, acc[1][kp * 2 + 1]);
            }
        }
#pragma unroll
        for (int p = 0; p < 2; p++)
#pragma unroll
            for (int k = 0; k < HH; k++) {
                float lo, hi;
                unpack2(acc[p][k], lo, hi);
                h2[p][k] = pack2(tanh_approx(lo), tanh_approx(hi));
            }
    }

    // output layer (w5 in regs)
    ull o2[2] = { s_b5d, s_b5d };
#pragma unroll
    for (int h = 0; h < HH; h++) {
        o2[0] = fma2(h2[0][h], w5d[h], o2[0]);
        o2[1] = fma2(h2[1][h], w5d[h], o2[1]);
    }
    float4 o4;
    unpack2(o2[0], o4.x, o4.y);
    unpack2(o2[1], o4.z, o4.w);
    *reinterpret_cast<float4*>(out + row) = o4;
}

// ---------------------------------------------------------------------------
extern "C" void kernel_launch(void* const* d_in, const int* in_sizes, int n_in,
                              void* d_out, int out_size) {
    const float* x  = (const float*)d_in[0];
    const float* A  = (const float*)d_in[1];
    const float* vp = (const float*)d_in[2];
    const float* W1 = (const float*)d_in[3];
    const float* b1 = (const float*)d_in[4];
    const float* W2 = (const float*)d_in[5];
    const float* b2 = (const float*)d_in[6];
    const float* W3 = (const float*)d_in[7];
    const float* b3 = (const float*)d_in[8];
    const float* W4 = (const float*)d_in[9];
    const float* b4 = (const float*)d_in[10];
    const float* W5 = (const float*)d_in[11];
    const float* b5 = (const float*)d_in[12];
    float* out = (float*)d_out;

    dim3 grid(NN / 32, NN / 32, BB);
    edge_mlp_kernel<<<grid, 256>>>(x, A, vp, W1, b1, W2, b2, W3, b3,
                                   W4, b4, W5, b5, out);
}

// round 5
// speedup vs baseline: 1.9300x; 1.0593x over previous
#include <cuda_runtime.h>
#include <cuda_bf16.h>

#define BB 2
#define NN 1024
#define DD 16
#define HH 8
#define W1STRIDE (3 * DD + 1)   // 49

typedef unsigned long long ull;

__device__ __forceinline__ float tanh_approx(float x) {
    float y;
    asm("tanh.approx.f32 %0, %1;" : "=f"(y) : "f"(x));
    return y;
}
__device__ __forceinline__ ull pack2(float lo, float hi) {
    ull d;
    asm("mov.b64 %0, {%1, %2};" : "=l"(d) : "f"(lo), "f"(hi));
    return d;
}
__device__ __forceinline__ void unpack2(ull v, float& lo, float& hi) {
    asm("mov.b64 {%0, %1}, %2;" : "=f"(lo), "=f"(hi) : "l"(v));
}
__device__ __forceinline__ ull fma2(ull a, ull b, ull c) {
    ull d;
    asm("fma.rn.f32x2 %0, %1, %2, %3;" : "=l"(d) : "l"(a), "l"(b), "l"(c));
    return d;
}
__device__ __forceinline__ ull add2(ull a, ull b) {
    ull d;
    asm("add.rn.f32x2 %0, %1, %2;" : "=l"(d) : "l"(a), "l"(b));
    return d;
}

// ---------------------------------------------------------------------------
// Fused kernel. Block = 256 threads = 32 i x 8 j-quads; 4 edges/thread as
// 2 packed f32x2 lanes. Register-lean (target 3 CTAs/SM): only the
// activation/accumulator core lives in registers; all weights are broadcast
// shared loads at point of use.
// ---------------------------------------------------------------------------
__global__ __launch_bounds__(256, 3)
void edge_mlp_kernel(const float* __restrict__ x,
                     const float* __restrict__ A,
                     const float* __restrict__ vp,
                     const float* __restrict__ W1, const float* __restrict__ b1,
                     const float* __restrict__ W2, const float* __restrict__ b2,
                     const float* __restrict__ W3, const float* __restrict__ b3,
                     const float* __restrict__ W4, const float* __restrict__ b4,
                     const float* __restrict__ W5, const float* __restrict__ b5,
                     float* __restrict__ out) {
    __shared__ __align__(16) float s_xj[32][DD];
    __shared__ __align__(16) float s_xi[32][DD];
    __shared__ __align__(16) float s_w1[HH * W1STRIDE];
    __shared__ __align__(16) float s_tjt[HH][32];     // t_j transposed [h][j]
    __shared__ __align__(16) float s_ti[32 * HH];     // t_i + t_v + b1, [i][h]
    __shared__ __align__(16) ull   s_wd[3][HH * HH];  // W-l transposed [h][k], dup pairs
    __shared__ __align__(16) ull   s_bd[3][HH];       // biases dup pairs
    __shared__ __align__(16) ull   s_w5d[HH];
    __shared__ __align__(16) ull   s_w1ad[HH];
    __shared__ ull   s_b5d;

    const int tid = threadIdx.x;
    const int b  = blockIdx.z;
    const int i0 = blockIdx.y * 32;
    const int j0 = blockIdx.x * 32;

    // --- phase 1: load x rows + all weights into shared ---
    {
        int row = tid >> 2;
        int c4  = (tid & 3) * 4;
        if (row < 32) {
            float4 v = *reinterpret_cast<const float4*>(x + ((size_t)(b * NN + j0 + row)) * DD + c4);
            s_xj[row][c4] = v.x; s_xj[row][c4 + 1] = v.y;
            s_xj[row][c4 + 2] = v.z; s_xj[row][c4 + 3] = v.w;
        } else {
            int r = row - 32;
            float4 v = *reinterpret_cast<const float4*>(x + ((size_t)(b * NN + i0 + r)) * DD + c4);
            s_xi[r][c4] = v.x; s_xi[r][c4 + 1] = v.y;
            s_xi[r][c4 + 2] = v.z; s_xi[r][c4 + 3] = v.w;
        }
        if (tid < HH * W1STRIDE - 256) s_w1[256 + tid] = W1[256 + tid];
        s_w1[tid] = W1[tid];
        if (tid < 64) {
            int dstT = (tid & 7) * HH + (tid >> 3);   // transpose to [h][k]
            float w2 = W2[tid], w3 = W3[tid], w4 = W4[tid];
            s_wd[0][dstT] = pack2(w2, w2);
            s_wd[1][dstT] = pack2(w3, w3);
            s_wd[2][dstT] = pack2(w4, w4);
        }
        if (tid < 8) {
            float v2 = b2[tid], v3 = b3[tid], v4 = b4[tid];
            s_bd[0][tid] = pack2(v2, v2);
            s_bd[1][tid] = pack2(v3, v3);
            s_bd[2][tid] = pack2(v4, v4);
            float w5 = W5[tid];
            s_w5d[tid] = pack2(w5, w5);
            float wa = W1[tid * W1STRIDE + 3 * DD];
            s_w1ad[tid] = pack2(wa, wa);
        }
        if (tid == 0) { float v = b5[0]; s_b5d = pack2(v, v); }
    }
    __syncthreads();

    const int ii = tid >> 3;         // 0..31
    const int jl = (tid & 7) * 4;    // 0,4,...,28

    // Early global A load to overlap with phase 2
    const size_t row = ((size_t)(b * NN + i0 + ii)) * NN + j0 + jl;
    float4 a4 = *reinterpret_cast<const float4*>(A + row);

    // --- phase 2: per-row projections ---
    {
        int n = tid >> 3;
        int h = tid & 7;
        const float* wr = s_w1 + h * W1STRIDE;
        float tj = 0.0f, ti = 0.0f;
#pragma unroll
        for (int c = 0; c < DD; c++) {
            tj += s_xj[n][c] * wr[c];
            ti += s_xi[n][c] * wr[DD + c];
        }
        float tv = b1[h];
#pragma unroll
        for (int c = 0; c < DD; c++)
            tv += vp[b * DD + c] * wr[2 * DD + c];
        s_tjt[h][n] = tj;
        s_ti[n * HH + h] = ti + tv;
    }
    __syncthreads();

    // --- phase 3: packed edge MLP (register-lean) ---
    ull a2lo = pack2(a4.x, a4.y);
    ull a2hi = pack2(a4.z, a4.w);

    // layer 1: weights + t_i read from shared at use (broadcast / small)
    ull h2[2][HH];
#pragma unroll
    for (int h = 0; h < HH; h++) {
        float4 tj4 = *reinterpret_cast<const float4*>(&s_tjt[h][jl]);
        float tival = s_ti[ii * HH + h];
        ull tiv = pack2(tival, tival);
        ull wa = s_w1ad[h];
        ull pre0 = fma2(a2lo, wa, add2(pack2(tj4.x, tj4.y), tiv));
        ull pre1 = fma2(a2hi, wa, add2(pack2(tj4.z, tj4.w), tiv));
        float l0, l1, l2, l3;
        unpack2(pre0, l0, l1);
        unpack2(pre1, l2, l3);
        h2[0][h] = pack2(tanh_approx(l0), tanh_approx(l1));
        h2[1][h] = pack2(tanh_approx(l2), tanh_approx(l3));
    }

    // layers 2..4: h outer, k inner; 16 independent acc chains
#pragma unroll
    for (int l = 0; l < 3; l++) {
        ull acc[2][HH];
#pragma unroll
        for (int k = 0; k < HH; k += 2) {
            ulonglong2 bk = *reinterpret_cast<const ulonglong2*>(&s_bd[l][k]);
            acc[0][k] = bk.x; acc[1][k] = bk.x;
            acc[0][k + 1] = bk.y; acc[1][k + 1] = bk.y;
        }
#pragma unroll
        for (int h = 0; h < HH; h++) {
            ull hv0 = h2[0][h];
            ull hv1 = h2[1][h];
#pragma unroll
            for (int kp = 0; kp < HH / 2; kp++) {
                ulonglong2 w = *reinterpret_cast<const ulonglong2*>(&s_wd[l][h * HH + kp * 2]);
                acc[0][kp * 2]     = fma2(hv0, w.x, acc[0][kp * 2]);
                acc[1][kp * 2]     = fma2(hv1, w.x, acc[1][kp * 2]);
                acc[0][kp * 2 + 1] = fma2(hv0, w.y, acc[0][kp * 2 + 1]);
                acc[1][kp * 2 + 1] = fma2(hv1, w.y, acc[1][kp * 2 + 1]);
            }
        }
#pragma unroll
        for (int p = 0; p < 2; p++)
#pragma unroll
            for (int k = 0; k < HH; k++) {
                float lo, hi;
                unpack2(acc[p][k], lo, hi);
                h2[p][k] = pack2(tanh_approx(lo), tanh_approx(hi));
            }
    }

    // output layer: w5 from shared at use (broadcast)
    ull o2lo = s_b5d, o2hi = s_b5d;
#pragma unroll
    for (int h = 0; h < HH; h++) {
        ull w = s_w5d[h];
        o2lo = fma2(h2[0][h], w, o2lo);
        o2hi = fma2(h2[1][h], w, o2hi);
    }
    float4 o4;
    unpack2(o2lo, o4.x, o4.y);
    unpack2(o2hi, o4.z, o4.w);
    *reinterpret_cast<float4*>(out + row) = o4;
}

// ---------------------------------------------------------------------------
extern "C" void kernel_launch(void* const* d_in, const int* in_sizes, int n_in,
                              void* d_out, int out_size) {
    const float* x  = (const float*)d_in[0];
    const float* A  = (const float*)d_in[1];
    const float* vp = (const float*)d_in[2];
    const float* W1 = (const float*)d_in[3];
    const float* b1 = (const float*)d_in[4];
    const float* W2 = (const float*)d_in[5];
    const float* b2 = (const float*)d_in[6];
    const float* W3 = (const float*)d_in[7];
    const float* b3 = (const float*)d_in[8];
    const float* W4 = (const float*)d_in[9];
    const float* b4 = (const float*)d_in[10];
    const float* W5 = (const float*)d_in[11];
    const float* b5 = (const float*)d_in[12];
    float* out = (float*)d_out;

    dim3 grid(NN / 32, NN / 32, BB);
    edge_mlp_kernel<<<grid, 256>>>(x, A, vp, W1, b1, W2, b2, W3, b3,
                                   W4, b4, W5, b5, out);
}